// round 15
// baseline (speedup 1.0000x reference)
#include <cuda_runtime.h>
#include <cuda_bf16.h>
#include <cuda_fp16.h>
#include <cstdint>
#include <cstddef>

#define NN 512
#define BN 2048
#define FD 64
#define EPSV 1e-14f

typedef unsigned long long ull;
typedef unsigned int u32;

// ---------------- scratch ----------------
__device__ float g_pj_ew[BN * FD];   // [n][k]  (coalesced column reads in pass 2)
__device__ float g_pi_ew[BN * FD];
__device__ float g_pjesT[BN * FD];   // [b][h][j]
__device__ float g_pi_es[BN * FD];
__device__ float g_pj_sa[BN];
__device__ float g_pi_sa[BN];

// ---------------- helpers ----------------
__device__ __forceinline__ float tanh_hw(float v) {
    float r; asm("tanh.approx.f32 %0, %1;" : "=f"(r) : "f"(v)); return r;
}
__device__ __forceinline__ float silu_hw(float v) {
    float m = 0.5f * v;
    return fmaf(m, tanh_hw(m), m);
}
__device__ __forceinline__ __half2 tanh_h2(__half2 v) {
    __half2 r;
    asm("tanh.approx.f16x2 %0, %1;" : "=r"(*(u32*)&r) : "r"(*(u32*)&v));
    return r;
}
// silu on two packed halves: m = v/2; m*tanh(m) + m
__device__ __forceinline__ __half2 silu_h2(__half2 v) {
    __half2 m = __hmul2(v, __float2half2_rn(0.5f));
    return __hfma2(m, tanh_h2(m), m);
}
__device__ __forceinline__ u32 h2u(__half2 h) { return *reinterpret_cast<u32*>(&h); }

// fp16 tensor-core MMA, fp32 accumulate (sm_80+, plain sm_103 target OK)
__device__ __forceinline__ void mma_f16_16x8x16(float d[4], const u32 a[4], u32 b0, u32 b1) {
    asm volatile("mma.sync.aligned.m16n8k16.row.col.f32.f16.f16.f32 "
        "{%0,%1,%2,%3}, {%4,%5,%6,%7}, {%8,%9}, {%0,%1,%2,%3};"
        : "+f"(d[0]), "+f"(d[1]), "+f"(d[2]), "+f"(d[3])
        : "r"(a[0]), "r"(a[1]), "r"(a[2]), "r"(a[3]), "r"(b0), "r"(b1));
}

#define APAD16 36   // u32 pitch per j row (144B: 8B-aligned stores; banks 4jj+lane distinct)

struct __align__(16) SMEM {
    u32 A16[8][16 * APAD16];   // per-warp he subtile, fp16x2 pairs [j(16)][hpair(32)]
    u32 Bpp[4 * FD * 8];       // W_c1 fp16x2: [kt(4)][m(64)][slot(8)], slot 2q+r <-> pair q+4r (8KB)
    float4 xmxv[NN];           // (dx, dy, dz, inv2)
    float filt[NN];
    float sw[NN];
    float piew[FD], pies[FD], wes0[FD], bc1[FD], wc2[FD];
    float attp[4][FD][3];
    float aggp[8][FD];
    float agg[FD], attn[FD];
    float xp[8][3];
    float red[8];
    float scal;
};

// ---------------- kernel A: node-level projections ----------------
__global__ void sake_pre(const float* __restrict__ h,
                         const float* __restrict__ W_ew,
                         const float* __restrict__ W_es,
                         const float* __restrict__ W_sa) {
    int n = blockIdx.x;
    int k = threadIdx.x;
    __shared__ float sh[FD];
    __shared__ float sp1[FD], sp2[FD];
    sh[k] = h[n * FD + k];
    __syncthreads();
    float a_jew = 0.f, a_iew = 0.f, a_jes = 0.f, a_ies = 0.f;
#pragma unroll 8
    for (int f = 0; f < FD; f++) {
        float hf = sh[f];
        a_jew = fmaf(hf, W_ew[f * FD + k], a_jew);
        a_iew = fmaf(hf, W_ew[(FD + f) * FD + k], a_iew);
        a_jes = fmaf(hf, W_es[(1 + f) * FD + k], a_jes);
        a_ies = fmaf(hf, W_es[(1 + FD + f) * FD + k], a_ies);
    }
    g_pj_ew[n * FD + k] = a_jew;
    g_pi_ew[n * FD + k] = a_iew;
    int b = n >> 9, j = n & 511;
    g_pjesT[(b * FD + k) * NN + j] = a_jes;
    g_pi_es[n * FD + k] = a_ies;
    sp1[k] = sh[k] * W_sa[k];
    sp2[k] = sh[k] * W_sa[FD + k];
    __syncthreads();
    if (k == 0) { float s = 0.f; for (int f = 0; f < FD; f++) s += sp1[f]; g_pj_sa[n] = s; }
    if (k == 1) { float s = 0.f; for (int f = 0; f < FD; f++) s += sp2[f]; g_pi_sa[n] = s; }
}

// ---------------- kernel B: fused pairwise main ----------------
__global__ __launch_bounds__(256, 3) void sake_main(
    const float* __restrict__ h, const float* __restrict__ x,
    const float* __restrict__ b_ew, const float* __restrict__ W_es,
    const float* __restrict__ b_es, const float* __restrict__ W_c1,
    const float* __restrict__ b_c1, const float* __restrict__ W_c2,
    const float* __restrict__ b_c2, const float* __restrict__ W_n,
    const float* __restrict__ b_n, float* __restrict__ out)
{
    extern __shared__ __align__(16) char dsm_raw[];
    SMEM* S = (SMEM*)dsm_raw;

    const int n_i = blockIdx.x;
    const int b = n_i >> 9;
    const int t = threadIdx.x;
    const int warp = t >> 5, lane = t & 31;

    // ---- stage Bpp: W_c1 as fp16x2 pairs.  slot s=2q+r holds k-pair p=q+4r of this kt block ----
    for (int idx = t; idx < 4 * FD * 8; idx += 256) {
        int s = idx & 7, m = (idx >> 3) & 63, kt = idx >> 9;
        int p = (s >> 1) + ((s & 1) << 2);
        int h0 = kt * 16 + 2 * p;
        S->Bpp[idx] = h2u(__floats2half2_rn(W_c1[h0 * FD + m], W_c1[(h0 + 1) * FD + m]));
    }
    if (t < FD) {
        S->piew[t] = g_pi_ew[n_i * FD + t] + b_ew[t];
        S->pies[t] = g_pi_es[n_i * FD + t] + b_es[t];
        S->wes0[t] = W_es[t];
        S->bc1[t]  = b_c1[t];
        S->wc2[t]  = W_c2[t];
    }

    const float xi0 = x[n_i * 3 + 0], xi1 = x[n_i * 3 + 1], xi2 = x[n_i * 3 + 2];
    const float pi_sa_v = g_pi_sa[n_i];
    const float bc2v = b_c2[0];

    // ---- pass 1: per-j geometry + softmax numerators ----
    float esum = 0.f;
    for (int j = t; j < NN; j += 256) {
        float dx = x[(b * NN + j) * 3 + 0] - xi0;
        float dy = x[(b * NN + j) * 3 + 1] - xi1;
        float dz = x[(b * NN + j) * 3 + 2] - xi2;
        float d2 = dx * dx + dy * dy + dz * dz;
        float nrm = sqrtf(d2 + EPSV);
        S->xmxv[j] = make_float4(dx, dy, dz, 1.0f / (nrm * nrm + EPSV));
        S->filt[j] = 1.0f / (nrm + 0.1f);
        float en = __expf(nrm);
        esum += en;
        float sem = g_pj_sa[b * NN + j] + pi_sa_v;
        sem = (sem > 0.f) ? sem : 0.01f * sem;
        S->sw[j] = sem * en;
    }
#pragma unroll
    for (int o = 16; o; o >>= 1) esum += __shfl_xor_sync(0xffffffffu, esum, o);
    if (lane == 0) S->red[warp] = esum;
    __syncthreads();
    if (t == 0) {
        float s = 0.f;
#pragma unroll
        for (int w = 0; w < 8; w++) s += S->red[w];
        S->scal = 1.0f / s;
    }
    __syncthreads();

    // ---- pass 2: att_sum einsum (coalesced column reads; f16x2 tanh on j-pairs) ----
    {
        int k = t & 63, jb2 = t >> 6;
        float base = S->piew[k];
        const float* pjew = g_pj_ew + (size_t)(b * NN) * FD + k;
        float a0 = 0.f, a1 = 0.f, a2 = 0.f;
        int j0 = jb2 * 128;
#pragma unroll 4
        for (int jj = 0; jj < 128; jj += 2) {
            int j = j0 + jj;
            float v0 = pjew[(size_t)j * FD] + base;
            float v1 = pjew[(size_t)(j + 1) * FD] + base;
            __half2 tpair = tanh_h2(__floats2half2_rn(v0, v1));
            float2 tf = __half22float2(tpair);
            float4 xv0 = S->xmxv[j];
            float4 xv1 = S->xmxv[j + 1];
            float e0 = tf.x * xv0.w;
            float e1 = tf.y * xv1.w;
            a0 = fmaf(e0, xv0.x, a0);
            a1 = fmaf(e0, xv0.y, a1);
            a2 = fmaf(e0, xv0.z, a2);
            a0 = fmaf(e1, xv1.x, a0);
            a1 = fmaf(e1, xv1.y, a1);
            a2 = fmaf(e1, xv1.z, a2);
        }
        S->attp[jb2][k][0] = a0; S->attp[jb2][k][1] = a1; S->attp[jb2][k][2] = a2;
    }
    __syncthreads();

    const float* pjes = g_pjesT + (size_t)(b * FD) * NN;
    u32* Aw16 = S->A16[warp];

    float xacc0 = 0.f, xacc1 = 0.f, xacc2 = 0.f;
    float agg0 = 0.f, agg1 = 0.f;     // lane owns h=2*lane, 2*lane+1 (unscaled)
    const int r4 = lane >> 2, c4 = lane & 3;
    const int row = lane >> 1, shalf = lane & 1;        // he-gen mapping
    const float bc2l = (c4 == 0) ? bc2v : 0.f;

    // ================= 4 subtiles of 16 j per warp =================
    for (int sub = 0; sub < 4; sub++) {
        const int jb = warp * 64 + sub * 16;

        // ---- he generation: 2 lanes per row, 32 h each -> fp16x2 silu ----
        {
            const int j = jb + row;
            const float filt = S->filt[j];
            const int h0b = shalf * 32;
#pragma unroll
            for (int q = 0; q < 8; q++) {
                const int h0 = h0b + q * 4;
                float p0 = pjes[(size_t)(h0 + 0) * NN + j] + fmaf(filt, S->wes0[h0 + 0], S->pies[h0 + 0]);
                float p1 = pjes[(size_t)(h0 + 1) * NN + j] + fmaf(filt, S->wes0[h0 + 1], S->pies[h0 + 1]);
                float p2 = pjes[(size_t)(h0 + 2) * NN + j] + fmaf(filt, S->wes0[h0 + 2], S->pies[h0 + 2]);
                float p3 = pjes[(size_t)(h0 + 3) * NN + j] + fmaf(filt, S->wes0[h0 + 3], S->pies[h0 + 3]);
                u32 lo = h2u(silu_h2(__floats2half2_rn(p0, p1)));
                u32 hi = h2u(silu_h2(__floats2half2_rn(p2, p3)));
                *(ull*)&Aw16[row * APAD16 + shalf * 16 + q * 2] = ((ull)hi << 32) | (ull)lo;
            }
        }
        __syncwarp();

        // ---- MMA: D[16j x 64m] = he @ W_c1 + b_c1, fp16 K=16 per step ----
        float D[8][4];
#pragma unroll
        for (int nt = 0; nt < 8; nt++) {
            const float bA = S->bc1[nt * 8 + 2 * c4], bB = S->bc1[nt * 8 + 2 * c4 + 1];
            D[nt][0] = bA; D[nt][1] = bB; D[nt][2] = bA; D[nt][3] = bB;
        }
#pragma unroll
        for (int kt = 0; kt < 4; kt++) {
            u32 a[4];
            a[0] = Aw16[r4 * APAD16 + kt * 8 + c4];
            a[1] = Aw16[(r4 + 8) * APAD16 + kt * 8 + c4];
            a[2] = Aw16[r4 * APAD16 + kt * 8 + 4 + c4];
            a[3] = Aw16[(r4 + 8) * APAD16 + kt * 8 + 4 + c4];
            const u32* bprow = S->Bpp + (kt << 9) + (c4 << 1);
#pragma unroll
            for (int nt = 0; nt < 8; nt++) {
                ull bv = *(const ull*)(bprow + ((nt * 8 + r4) << 3));
                mma_f16_16x8x16(D[nt], a, (u32)bv, (u32)(bv >> 32));
            }
        }

        // ---- epilogue: f16x2 silu -> f32 dot wc2 -> shuffle-free partial-coord x accum ----
        {
            float cs0 = bc2l, cs1 = bc2l;
#pragma unroll
            for (int nt = 0; nt < 8; nt++) {
                const int c0 = nt * 8 + 2 * c4, c1 = c0 + 1;
                const float wcA = S->wc2[c0], wcB = S->wc2[c1];
                float2 u01 = __half22float2(silu_h2(__floats2half2_rn(D[nt][0], D[nt][1])));
                float2 u23 = __half22float2(silu_h2(__floats2half2_rn(D[nt][2], D[nt][3])));
                cs0 = fmaf(u01.x, wcA, cs0);
                cs0 = fmaf(u01.y, wcB, cs0);
                cs1 = fmaf(u23.x, wcA, cs1);
                cs1 = fmaf(u23.y, wcB, cs1);
            }
            const int j0 = jb + r4, j1 = j0 + 8;
            float4 xv0 = S->xmxv[j0];
            float4 xv1 = S->xmxv[j1];
            xacc0 = fmaf(xv0.x, cs0, xacc0);
            xacc1 = fmaf(xv0.y, cs0, xacc1);
            xacc2 = fmaf(xv0.z, cs0, xacc2);
            xacc0 = fmaf(xv1.x, cs1, xacc0);
            xacc1 = fmaf(xv1.y, cs1, xacc1);
            xacc2 = fmaf(xv1.z, cs1, xacc2);
        }

        // ---- h_e_agg from staged fp16 pairs (banks (4*jj+lane)%32: conflict-free) ----
#pragma unroll 4
        for (int jj = 0; jj < 16; jj++) {
            float w = S->sw[jb + jj];
            u32 v = Aw16[jj * APAD16 + lane];
            __half2 h2v = *reinterpret_cast<__half2*>(&v);
            float2 f2 = __half22float2(h2v);
            agg0 = fmaf(w, f2.x, agg0);
            agg1 = fmaf(w, f2.y, agg1);
        }
        __syncwarp();   // A reused next subtile
    }

    // lane owns h = 2*lane (agg0), 2*lane+1 (agg1)
    S->aggp[warp][2 * lane]     = agg0;
    S->aggp[warp][2 * lane + 1] = agg1;
#pragma unroll
    for (int o = 16; o; o >>= 1) {
        xacc0 += __shfl_xor_sync(0xffffffffu, xacc0, o);
        xacc1 += __shfl_xor_sync(0xffffffffu, xacc1, o);
        xacc2 += __shfl_xor_sync(0xffffffffu, xacc2, o);
    }
    if (lane == 0) { S->xp[warp][0] = xacc0; S->xp[warp][1] = xacc1; S->xp[warp][2] = xacc2; }
    __syncthreads();

    // ---- finalize att_norm and h_e_agg (softmax scale folded in here) ----
    if (t < FD) {
        float a0 = S->attp[0][t][0] + S->attp[1][t][0] + S->attp[2][t][0] + S->attp[3][t][0];
        float a1 = S->attp[0][t][1] + S->attp[1][t][1] + S->attp[2][t][1] + S->attp[3][t][1];
        float a2 = S->attp[0][t][2] + S->attp[1][t][2] + S->attp[2][t][2] + S->attp[3][t][2];
        S->attn[t] = sqrtf(a0 * a0 + a1 * a1 + a2 * a2 + EPSV);
        float ag = 0.f;
#pragma unroll
        for (int w2 = 0; w2 < 8; w2++) ag += S->aggp[w2][t];
        S->agg[t] = ag * S->scal;
    }
    __syncthreads();

    // ---- h_new = concat(h, agg, attn) @ W_n + b_n ----
    if (t < FD) {
        int m = t;
        float acc = b_n[m];
        const float* hi2 = h + (size_t)n_i * FD;
#pragma unroll 8
        for (int f = 0; f < FD; f++)  acc = fmaf(hi2[f],      W_n[f * FD + m], acc);
#pragma unroll 8
        for (int f = 0; f < FD; f++)  acc = fmaf(S->agg[f],   W_n[(FD + f) * FD + m], acc);
#pragma unroll 8
        for (int f = 0; f < FD; f++)  acc = fmaf(S->attn[f],  W_n[(2 * FD + f) * FD + m], acc);
        out[(size_t)n_i * FD + m] = acc;
    }
    if (t >= 64 && t < 67) {
        int c = t - 64;
        float xs = 0.f;
#pragma unroll
        for (int w2 = 0; w2 < 8; w2++) xs += S->xp[w2][c];
        out[(size_t)BN * FD + n_i * 3 + c] = x[n_i * 3 + c] + xs;
    }
}

extern "C" void kernel_launch(void* const* d_in, const int* in_sizes, int n_in,
                              void* d_out, int out_size) {
    const float* h    = (const float*)d_in[0];
    const float* x    = (const float*)d_in[1];
    const float* W_ew = (const float*)d_in[2];
    const float* b_ew = (const float*)d_in[3];
    const float* W_sa = (const float*)d_in[4];
    const float* W_es = (const float*)d_in[5];
    const float* b_es = (const float*)d_in[6];
    const float* W_c1 = (const float*)d_in[7];
    const float* b_c1 = (const float*)d_in[8];
    const float* W_c2 = (const float*)d_in[9];
    const float* b_c2 = (const float*)d_in[10];
    const float* W_n  = (const float*)d_in[11];
    const float* b_n  = (const float*)d_in[12];
    float* out = (float*)d_out;

    const int smem_bytes = (int)sizeof(SMEM);
    cudaFuncSetAttribute(sake_main, cudaFuncAttributeMaxDynamicSharedMemorySize, smem_bytes);

    sake_pre<<<BN, 64>>>(h, W_ew, W_es, W_sa);
    sake_main<<<BN, 256, smem_bytes>>>(h, x, b_ew, W_es, b_es, W_c1, b_c1, W_c2, b_c2, W_n, b_n, out);
}

// round 16
// speedup vs baseline: 1.0073x; 1.0073x over previous
#include <cuda_runtime.h>
#include <cuda_bf16.h>
#include <cuda_fp16.h>
#include <cstdint>
#include <cstddef>

#define NN 512
#define BN 2048
#define FD 64
#define EPSV 1e-14f

typedef unsigned long long ull;
typedef unsigned int u32;

// ---------------- scratch ----------------
__device__ float g_pj_ew[BN * FD];   // [n][k]  (coalesced column reads in pass 2)
__device__ float g_pi_ew[BN * FD];
__device__ float g_pjesT[BN * FD];   // [b][h][j]
__device__ float g_pi_es[BN * FD];
__device__ float g_pj_sa[BN];
__device__ float g_pi_sa[BN];

// ---------------- helpers ----------------
__device__ __forceinline__ float tanh_hw(float v) {
    float r; asm("tanh.approx.f32 %0, %1;" : "=f"(r) : "f"(v)); return r;
}
__device__ __forceinline__ float silu_hw(float v) {
    float m = 0.5f * v;
    return fmaf(m, tanh_hw(m), m);
}
__device__ __forceinline__ u32 packh2(float lo, float hi) {
    __half2 h = __floats2half2_rn(lo, hi);
    return *reinterpret_cast<u32*>(&h);
}

// fp16 tensor-core MMA, fp32 accumulate (sm_80+, plain sm_103 target OK)
__device__ __forceinline__ void mma_f16_16x8x16(float d[4], const u32 a[4], u32 b0, u32 b1) {
    asm volatile("mma.sync.aligned.m16n8k16.row.col.f32.f16.f16.f32 "
        "{%0,%1,%2,%3}, {%4,%5,%6,%7}, {%8,%9}, {%0,%1,%2,%3};"
        : "+f"(d[0]), "+f"(d[1]), "+f"(d[2]), "+f"(d[3])
        : "r"(a[0]), "r"(a[1]), "r"(a[2]), "r"(a[3]), "r"(b0), "r"(b1));
}

#define APAD16 36   // u32 pitch per j row (144B: 8B-aligned stores; banks 4jj+lane distinct)

struct __align__(16) SMEM {
    u32 A16[8][16 * APAD16];   // per-warp he subtile, fp16x2 pairs [j(16)][hpair(32)]
    u32 Bpp[4 * FD * 8];       // W_c1 fp16x2: [kt(4)][m(64)][slot(8)], slot 2q+r <-> pair q+4r (8KB)
    float4 xmxv[NN];           // (dx, dy, dz, inv2)
    float filt[NN];
    float sw[NN];
    float piew[FD], pies[FD], wes0[FD], bc1[FD], wc2[FD];
    float attp[4][FD][3];
    float aggp[8][FD];
    float agg[FD], attn[FD];
    float xp[8][3];
    float red[8];
    float scal;
};

// ---------------- kernel A: node-level projections ----------------
__global__ void sake_pre(const float* __restrict__ h,
                         const float* __restrict__ W_ew,
                         const float* __restrict__ W_es,
                         const float* __restrict__ W_sa) {
    int n = blockIdx.x;
    int k = threadIdx.x;
    __shared__ float sh[FD];
    __shared__ float sp1[FD], sp2[FD];
    sh[k] = h[n * FD + k];
    __syncthreads();
    float a_jew = 0.f, a_iew = 0.f, a_jes = 0.f, a_ies = 0.f;
#pragma unroll 8
    for (int f = 0; f < FD; f++) {
        float hf = sh[f];
        a_jew = fmaf(hf, W_ew[f * FD + k], a_jew);
        a_iew = fmaf(hf, W_ew[(FD + f) * FD + k], a_iew);
        a_jes = fmaf(hf, W_es[(1 + f) * FD + k], a_jes);
        a_ies = fmaf(hf, W_es[(1 + FD + f) * FD + k], a_ies);
    }
    g_pj_ew[n * FD + k] = a_jew;
    g_pi_ew[n * FD + k] = a_iew;
    int b = n >> 9, j = n & 511;
    g_pjesT[(b * FD + k) * NN + j] = a_jes;
    g_pi_es[n * FD + k] = a_ies;
    sp1[k] = sh[k] * W_sa[k];
    sp2[k] = sh[k] * W_sa[FD + k];
    __syncthreads();
    if (k == 0) { float s = 0.f; for (int f = 0; f < FD; f++) s += sp1[f]; g_pj_sa[n] = s; }
    if (k == 1) { float s = 0.f; for (int f = 0; f < FD; f++) s += sp2[f]; g_pi_sa[n] = s; }
}

// ---------------- kernel B: fused pairwise main ----------------
__global__ __launch_bounds__(256, 4) void sake_main(
    const float* __restrict__ h, const float* __restrict__ x,
    const float* __restrict__ b_ew, const float* __restrict__ W_es,
    const float* __restrict__ b_es, const float* __restrict__ W_c1,
    const float* __restrict__ b_c1, const float* __restrict__ W_c2,
    const float* __restrict__ b_c2, const float* __restrict__ W_n,
    const float* __restrict__ b_n, float* __restrict__ out)
{
    extern __shared__ __align__(16) char dsm_raw[];
    SMEM* S = (SMEM*)dsm_raw;

    const int n_i = blockIdx.x;
    const int b = n_i >> 9;
    const int t = threadIdx.x;
    const int warp = t >> 5, lane = t & 31;

    // ---- stage Bpp: W_c1 as fp16x2 pairs.  slot s=2q+r holds k-pair p=q+4r of this kt block ----
    for (int idx = t; idx < 4 * FD * 8; idx += 256) {
        int s = idx & 7, m = (idx >> 3) & 63, kt = idx >> 9;
        int p = (s >> 1) + ((s & 1) << 2);
        int h0 = kt * 16 + 2 * p;
        S->Bpp[idx] = packh2(W_c1[h0 * FD + m], W_c1[(h0 + 1) * FD + m]);
    }
    if (t < FD) {
        S->piew[t] = g_pi_ew[n_i * FD + t] + b_ew[t];
        S->pies[t] = g_pi_es[n_i * FD + t] + b_es[t];
        S->wes0[t] = W_es[t];
        S->bc1[t]  = b_c1[t];
        S->wc2[t]  = W_c2[t];
    }

    const float xi0 = x[n_i * 3 + 0], xi1 = x[n_i * 3 + 1], xi2 = x[n_i * 3 + 2];
    const float pi_sa_v = g_pi_sa[n_i];
    const float bc2v = b_c2[0];

    // ---- pass 1: per-j geometry + softmax numerators ----
    float esum = 0.f;
    for (int j = t; j < NN; j += 256) {
        float dx = x[(b * NN + j) * 3 + 0] - xi0;
        float dy = x[(b * NN + j) * 3 + 1] - xi1;
        float dz = x[(b * NN + j) * 3 + 2] - xi2;
        float d2 = dx * dx + dy * dy + dz * dz;
        float nrm = sqrtf(d2 + EPSV);
        S->xmxv[j] = make_float4(dx, dy, dz, 1.0f / (nrm * nrm + EPSV));
        S->filt[j] = 1.0f / (nrm + 0.1f);
        float en = __expf(nrm);
        esum += en;
        float sem = g_pj_sa[b * NN + j] + pi_sa_v;
        sem = (sem > 0.f) ? sem : 0.01f * sem;
        S->sw[j] = sem * en;
    }
#pragma unroll
    for (int o = 16; o; o >>= 1) esum += __shfl_xor_sync(0xffffffffu, esum, o);
    if (lane == 0) S->red[warp] = esum;
    __syncthreads();
    if (t == 0) {
        float s = 0.f;
#pragma unroll
        for (int w = 0; w < 8; w++) s += S->red[w];
        S->scal = 1.0f / s;
    }
    __syncthreads();

    // ---- pass 2: att_sum einsum (coalesced column reads; float4 geometry) ----
    {
        int k = t & 63, jb2 = t >> 6;
        float base = S->piew[k];
        const float* pjew = g_pj_ew + (size_t)(b * NN) * FD + k;
        float a0 = 0.f, a1 = 0.f, a2 = 0.f;
        int j0 = jb2 * 128;
#pragma unroll 8
        for (int jj = 0; jj < 128; jj++) {
            int j = j0 + jj;
            float4 xv = S->xmxv[j];
            float e = tanh_hw(pjew[(size_t)j * FD] + base) * xv.w;
            a0 = fmaf(e, xv.x, a0);
            a1 = fmaf(e, xv.y, a1);
            a2 = fmaf(e, xv.z, a2);
        }
        S->attp[jb2][k][0] = a0; S->attp[jb2][k][1] = a1; S->attp[jb2][k][2] = a2;
    }
    __syncthreads();

    const float* pjes = g_pjesT + (size_t)(b * FD) * NN;
    u32* Aw16 = S->A16[warp];

    float xacc0 = 0.f, xacc1 = 0.f, xacc2 = 0.f;
    float agg0 = 0.f, agg1 = 0.f;     // lane owns h=2*lane, 2*lane+1 (unscaled)
    const int r4 = lane >> 2, c4 = lane & 3;
    const int row = lane >> 1, shalf = lane & 1;        // he-gen mapping
    const float bc2l = (c4 == 0) ? bc2v : 0.f;

    // ================= 4 subtiles of 16 j per warp =================
    for (int sub = 0; sub < 4; sub++) {
        const int jb = warp * 64 + sub * 16;

        // ---- he generation: 2 lanes per row, 32 h each -> fp16x2 pairs ----
        {
            const int j = jb + row;
            const float filt = S->filt[j];
            const int h0b = shalf * 32;
#pragma unroll
            for (int q = 0; q < 8; q++) {
                const int h0 = h0b + q * 4;
                float p0 = pjes[(size_t)(h0 + 0) * NN + j] + fmaf(filt, S->wes0[h0 + 0], S->pies[h0 + 0]);
                float p1 = pjes[(size_t)(h0 + 1) * NN + j] + fmaf(filt, S->wes0[h0 + 1], S->pies[h0 + 1]);
                float p2 = pjes[(size_t)(h0 + 2) * NN + j] + fmaf(filt, S->wes0[h0 + 2], S->pies[h0 + 2]);
                float p3 = pjes[(size_t)(h0 + 3) * NN + j] + fmaf(filt, S->wes0[h0 + 3], S->pies[h0 + 3]);
                u32 lo = packh2(silu_hw(p0), silu_hw(p1));
                u32 hi = packh2(silu_hw(p2), silu_hw(p3));
                *(ull*)&Aw16[row * APAD16 + shalf * 16 + q * 2] = ((ull)hi << 32) | (ull)lo;
            }
        }
        __syncwarp();

        // ---- MMA + epilogue in two m-halves (D live = 16 regs -> 64-reg kernel, 4 blocks/SM) ----
        float cs0 = bc2l, cs1 = bc2l;
#pragma unroll
        for (int half = 0; half < 2; half++) {
            float D[4][4];
#pragma unroll
            for (int nt = 0; nt < 4; nt++) {
                const int m0 = (half * 4 + nt) * 8 + 2 * c4;
                const float bA = S->bc1[m0], bB = S->bc1[m0 + 1];
                D[nt][0] = bA; D[nt][1] = bB; D[nt][2] = bA; D[nt][3] = bB;
            }
#pragma unroll
            for (int kt = 0; kt < 4; kt++) {
                u32 a[4];
                a[0] = Aw16[r4 * APAD16 + kt * 8 + c4];
                a[1] = Aw16[(r4 + 8) * APAD16 + kt * 8 + c4];
                a[2] = Aw16[r4 * APAD16 + kt * 8 + 4 + c4];
                a[3] = Aw16[(r4 + 8) * APAD16 + kt * 8 + 4 + c4];
                const u32* bprow = S->Bpp + (kt << 9) + (c4 << 1);
#pragma unroll
                for (int nt = 0; nt < 4; nt++) {
                    const int ntg = half * 4 + nt;
                    ull bv = *(const ull*)(bprow + ((ntg * 8 + r4) << 3));
                    mma_f16_16x8x16(D[nt], a, (u32)bv, (u32)(bv >> 32));
                }
            }
#pragma unroll
            for (int nt = 0; nt < 4; nt++) {
                const int c0 = (half * 4 + nt) * 8 + 2 * c4, c1 = c0 + 1;
                const float wcA = S->wc2[c0], wcB = S->wc2[c1];
                cs0 = fmaf(silu_hw(D[nt][0]), wcA, cs0);
                cs0 = fmaf(silu_hw(D[nt][1]), wcB, cs0);
                cs1 = fmaf(silu_hw(D[nt][2]), wcA, cs1);
                cs1 = fmaf(silu_hw(D[nt][3]), wcB, cs1);
            }
        }

        // partial coords -> x accumulation (butterfly at end completes j- and c4-sums)
        {
            const int j0 = jb + r4, j1 = j0 + 8;
            float4 xv0 = S->xmxv[j0];
            float4 xv1 = S->xmxv[j1];
            xacc0 = fmaf(xv0.x, cs0, xacc0);
            xacc1 = fmaf(xv0.y, cs0, xacc1);
            xacc2 = fmaf(xv0.z, cs0, xacc2);
            xacc0 = fmaf(xv1.x, cs1, xacc0);
            xacc1 = fmaf(xv1.y, cs1, xacc1);
            xacc2 = fmaf(xv1.z, cs1, xacc2);
        }

        // ---- h_e_agg from staged fp16 pairs (banks (4*jj+lane)%32: conflict-free) ----
#pragma unroll 4
        for (int jj = 0; jj < 16; jj++) {
            float w = S->sw[jb + jj];
            u32 v = Aw16[jj * APAD16 + lane];
            __half2 h2v = *reinterpret_cast<__half2*>(&v);
            float2 f2 = __half22float2(h2v);
            agg0 = fmaf(w, f2.x, agg0);
            agg1 = fmaf(w, f2.y, agg1);
        }
        __syncwarp();   // A reused next subtile
    }

    // lane owns h = 2*lane (agg0), 2*lane+1 (agg1)
    S->aggp[warp][2 * lane]     = agg0;
    S->aggp[warp][2 * lane + 1] = agg1;
#pragma unroll
    for (int o = 16; o; o >>= 1) {
        xacc0 += __shfl_xor_sync(0xffffffffu, xacc0, o);
        xacc1 += __shfl_xor_sync(0xffffffffu, xacc1, o);
        xacc2 += __shfl_xor_sync(0xffffffffu, xacc2, o);
    }
    if (lane == 0) { S->xp[warp][0] = xacc0; S->xp[warp][1] = xacc1; S->xp[warp][2] = xacc2; }
    __syncthreads();

    // ---- finalize att_norm and h_e_agg (softmax scale folded in here) ----
    if (t < FD) {
        float a0 = S->attp[0][t][0] + S->attp[1][t][0] + S->attp[2][t][0] + S->attp[3][t][0];
        float a1 = S->attp[0][t][1] + S->attp[1][t][1] + S->attp[2][t][1] + S->attp[3][t][1];
        float a2 = S->attp[0][t][2] + S->attp[1][t][2] + S->attp[2][t][2] + S->attp[3][t][2];
        S->attn[t] = sqrtf(a0 * a0 + a1 * a1 + a2 * a2 + EPSV);
        float ag = 0.f;
#pragma unroll
        for (int w2 = 0; w2 < 8; w2++) ag += S->aggp[w2][t];
        S->agg[t] = ag * S->scal;
    }
    __syncthreads();

    // ---- h_new = concat(h, agg, attn) @ W_n + b_n ----
    if (t < FD) {
        int m = t;
        float acc = b_n[m];
        const float* hi2 = h + (size_t)n_i * FD;
#pragma unroll 8
        for (int f = 0; f < FD; f++)  acc = fmaf(hi2[f],      W_n[f * FD + m], acc);
#pragma unroll 8
        for (int f = 0; f < FD; f++)  acc = fmaf(S->agg[f],   W_n[(FD + f) * FD + m], acc);
#pragma unroll 8
        for (int f = 0; f < FD; f++)  acc = fmaf(S->attn[f],  W_n[(2 * FD + f) * FD + m], acc);
        out[(size_t)n_i * FD + m] = acc;
    }
    if (t >= 64 && t < 67) {
        int c = t - 64;
        float xs = 0.f;
#pragma unroll
        for (int w2 = 0; w2 < 8; w2++) xs += S->xp[w2][c];
        out[(size_t)BN * FD + n_i * 3 + c] = x[n_i * 3 + c] + xs;
    }
}

extern "C" void kernel_launch(void* const* d_in, const int* in_sizes, int n_in,
                              void* d_out, int out_size) {
    const float* h    = (const float*)d_in[0];
    const float* x    = (const float*)d_in[1];
    const float* W_ew = (const float*)d_in[2];
    const float* b_ew = (const float*)d_in[3];
    const float* W_sa = (const float*)d_in[4];
    const float* W_es = (const float*)d_in[5];
    const float* b_es = (const float*)d_in[6];
    const float* W_c1 = (const float*)d_in[7];
    const float* b_c1 = (const float*)d_in[8];
    const float* W_c2 = (const float*)d_in[9];
    const float* b_c2 = (const float*)d_in[10];
    const float* W_n  = (const float*)d_in[11];
    const float* b_n  = (const float*)d_in[12];
    float* out = (float*)d_out;

    const int smem_bytes = (int)sizeof(SMEM);
    cudaFuncSetAttribute(sake_main, cudaFuncAttributeMaxDynamicSharedMemorySize, smem_bytes);

    sake_pre<<<BN, 64>>>(h, W_ew, W_es, W_sa);
    sake_main<<<BN, 256, smem_bytes>>>(h, x, b_ew, W_es, b_es, W_c1, b_c1, W_c2, b_c2, W_n, b_n, out);
}

// round 17
// speedup vs baseline: 1.0413x; 1.0338x over previous
#include <cuda_runtime.h>
#include <cuda_bf16.h>
#include <cuda_fp16.h>
#include <cstdint>
#include <cstddef>

#define NN 512
#define BN 2048
#define FD 64
#define EPSV 1e-14f

typedef unsigned long long ull;
typedef unsigned int u32;

// ---------------- scratch ----------------
__device__ float g_pj_ew[BN * FD];   // [n][k]  (coalesced column reads in pass 2)
__device__ float g_pi_ew[BN * FD];
__device__ float g_pjesT[BN * FD];   // [b][h][j]
__device__ float g_pi_es[BN * FD];
__device__ float g_pj_sa[BN];
__device__ float g_pi_sa[BN];

// ---------------- helpers ----------------
__device__ __forceinline__ float tanh_hw(float v) {
    float r; asm("tanh.approx.f32 %0, %1;" : "=f"(r) : "f"(v)); return r;
}
__device__ __forceinline__ float silu_hw(float v) {
    float m = 0.5f * v;
    return fmaf(m, tanh_hw(m), m);
}
__device__ __forceinline__ u32 packh2(float lo, float hi) {
    __half2 h = __floats2half2_rn(lo, hi);
    return *reinterpret_cast<u32*>(&h);
}

// fp16 tensor-core MMA, fp32 accumulate (sm_80+, plain sm_103 target OK)
__device__ __forceinline__ void mma_f16_16x8x16(float d[4], const u32 a[4], u32 b0, u32 b1) {
    asm volatile("mma.sync.aligned.m16n8k16.row.col.f32.f16.f16.f32 "
        "{%0,%1,%2,%3}, {%4,%5,%6,%7}, {%8,%9}, {%0,%1,%2,%3};"
        : "+f"(d[0]), "+f"(d[1]), "+f"(d[2]), "+f"(d[3])
        : "r"(a[0]), "r"(a[1]), "r"(a[2]), "r"(a[3]), "r"(b0), "r"(b1));
}

#define STS128S(ad, r0, r1, r2, r3) \
    asm volatile("st.shared.v4.b32 [%0], {%1,%2,%3,%4};" :: "r"(ad), "r"(r0), "r"(r1), "r"(r2), "r"(r3) : "memory")

#define APAD16 36   // u32 pitch per j row (144B: 16B-aligned v4 stores; banks 4jj+lane distinct)

struct __align__(16) SMEM {
    u32 A16[8][16 * APAD16];   // per-warp he subtile, fp16x2 pairs [j(16)][hpair(32)]
    u32 Bpp[4 * FD * 8];       // W_c1 fp16x2: [kt(4)][m(64)][slot(8)], slot 2q+r <-> pair q+4r (8KB)
    float4 xmxv[NN];           // (dx, dy, dz, inv2)
    float filt[NN];
    float sw[NN];
    float piew[FD], pies[FD], wes0[FD], bc1[FD], wc2[FD];
    float attp[4][FD][3];
    float aggp[8][FD];
    float agg[FD], attn[FD];
    float xp[8][3];
    float red[8];
    float scal;
};

// ---------------- kernel A: node-level projections ----------------
__global__ void sake_pre(const float* __restrict__ h,
                         const float* __restrict__ W_ew,
                         const float* __restrict__ W_es,
                         const float* __restrict__ W_sa) {
    int n = blockIdx.x;
    int k = threadIdx.x;
    __shared__ float sh[FD];
    __shared__ float sp1[FD], sp2[FD];
    sh[k] = h[n * FD + k];
    __syncthreads();
    float a_jew = 0.f, a_iew = 0.f, a_jes = 0.f, a_ies = 0.f;
#pragma unroll 8
    for (int f = 0; f < FD; f++) {
        float hf = sh[f];
        a_jew = fmaf(hf, W_ew[f * FD + k], a_jew);
        a_iew = fmaf(hf, W_ew[(FD + f) * FD + k], a_iew);
        a_jes = fmaf(hf, W_es[(1 + f) * FD + k], a_jes);
        a_ies = fmaf(hf, W_es[(1 + FD + f) * FD + k], a_ies);
    }
    g_pj_ew[n * FD + k] = a_jew;
    g_pi_ew[n * FD + k] = a_iew;
    int b = n >> 9, j = n & 511;
    g_pjesT[(b * FD + k) * NN + j] = a_jes;
    g_pi_es[n * FD + k] = a_ies;
    sp1[k] = sh[k] * W_sa[k];
    sp2[k] = sh[k] * W_sa[FD + k];
    __syncthreads();
    if (k == 0) { float s = 0.f; for (int f = 0; f < FD; f++) s += sp1[f]; g_pj_sa[n] = s; }
    if (k == 1) { float s = 0.f; for (int f = 0; f < FD; f++) s += sp2[f]; g_pi_sa[n] = s; }
}

// ---------------- kernel B: fused pairwise main ----------------
__global__ __launch_bounds__(256, 3) void sake_main(
    const float* __restrict__ h, const float* __restrict__ x,
    const float* __restrict__ b_ew, const float* __restrict__ W_es,
    const float* __restrict__ b_es, const float* __restrict__ W_c1,
    const float* __restrict__ b_c1, const float* __restrict__ W_c2,
    const float* __restrict__ b_c2, const float* __restrict__ W_n,
    const float* __restrict__ b_n, float* __restrict__ out)
{
    extern __shared__ __align__(16) char dsm_raw[];
    SMEM* S = (SMEM*)dsm_raw;

    const int n_i = blockIdx.x;
    const int b = n_i >> 9;
    const int t = threadIdx.x;
    const int warp = t >> 5, lane = t & 31;

    // ---- stage Bpp: W_c1 as fp16x2 pairs.  slot s=2q+r holds k-pair p=q+4r of this kt block ----
    for (int idx = t; idx < 4 * FD * 8; idx += 256) {
        int s = idx & 7, m = (idx >> 3) & 63, kt = idx >> 9;
        int p = (s >> 1) + ((s & 1) << 2);
        int h0 = kt * 16 + 2 * p;
        S->Bpp[idx] = packh2(W_c1[h0 * FD + m], W_c1[(h0 + 1) * FD + m]);
    }
    if (t < FD) {
        S->piew[t] = g_pi_ew[n_i * FD + t] + b_ew[t];
        S->pies[t] = g_pi_es[n_i * FD + t] + b_es[t];
        S->wes0[t] = W_es[t];
        S->bc1[t]  = b_c1[t];
        S->wc2[t]  = W_c2[t];
    }

    const float xi0 = x[n_i * 3 + 0], xi1 = x[n_i * 3 + 1], xi2 = x[n_i * 3 + 2];
    const float pi_sa_v = g_pi_sa[n_i];
    const float bc2v = b_c2[0];

    // ---- pass 1: per-j geometry + softmax numerators ----
    float esum = 0.f;
    for (int j = t; j < NN; j += 256) {
        float dx = x[(b * NN + j) * 3 + 0] - xi0;
        float dy = x[(b * NN + j) * 3 + 1] - xi1;
        float dz = x[(b * NN + j) * 3 + 2] - xi2;
        float d2 = dx * dx + dy * dy + dz * dz;
        float nrm = sqrtf(d2 + EPSV);
        S->xmxv[j] = make_float4(dx, dy, dz, 1.0f / (nrm * nrm + EPSV));
        S->filt[j] = 1.0f / (nrm + 0.1f);
        float en = __expf(nrm);
        esum += en;
        float sem = g_pj_sa[b * NN + j] + pi_sa_v;
        sem = (sem > 0.f) ? sem : 0.01f * sem;
        S->sw[j] = sem * en;
    }
#pragma unroll
    for (int o = 16; o; o >>= 1) esum += __shfl_xor_sync(0xffffffffu, esum, o);
    if (lane == 0) S->red[warp] = esum;
    __syncthreads();
    if (t == 0) {
        float s = 0.f;
#pragma unroll
        for (int w = 0; w < 8; w++) s += S->red[w];
        S->scal = 1.0f / s;
    }
    __syncthreads();

    // ---- pass 2: att_sum einsum (coalesced column reads; float4 geometry) ----
    {
        int k = t & 63, jb2 = t >> 6;
        float base = S->piew[k];
        const float* pjew = g_pj_ew + (size_t)(b * NN) * FD + k;
        float a0 = 0.f, a1 = 0.f, a2 = 0.f;
        int j0 = jb2 * 128;
#pragma unroll 8
        for (int jj = 0; jj < 128; jj++) {
            int j = j0 + jj;
            float4 xv = S->xmxv[j];
            float e = tanh_hw(pjew[(size_t)j * FD] + base) * xv.w;
            a0 = fmaf(e, xv.x, a0);
            a1 = fmaf(e, xv.y, a1);
            a2 = fmaf(e, xv.z, a2);
        }
        S->attp[jb2][k][0] = a0; S->attp[jb2][k][1] = a1; S->attp[jb2][k][2] = a2;
    }
    // NO __syncthreads here: pass 3 touches only A16[warp]/aggp/xp + pass-1 data;
    // attp is consumed only after the post-pass-3 __syncthreads below.

    const float* pjes = g_pjesT + (size_t)(b * FD) * NN;
    u32* Aw16 = S->A16[warp];
    const u32 Aw_ad = (u32)__cvta_generic_to_shared(Aw16);

    float xacc0 = 0.f, xacc1 = 0.f, xacc2 = 0.f;
    float agg0 = 0.f, agg1 = 0.f;     // lane owns h=2*lane, 2*lane+1 (unscaled)
    const int r4 = lane >> 2, c4 = lane & 3;
    const int row = lane >> 1, shalf = lane & 1;        // he-gen mapping
    const float bc2l = (c4 == 0) ? bc2v : 0.f;

    // ================= 4 subtiles of 16 j per warp =================
    for (int sub = 0; sub < 4; sub++) {
        const int jb = warp * 64 + sub * 16;

        // ---- he generation: 2 lanes per row, 32 h each -> fp16x2 pairs, STS.128 ----
        {
            const int j = jb + row;
            const float filt = S->filt[j];
            const int h0b = shalf * 32;
#pragma unroll
            for (int q = 0; q < 8; q += 2) {
                const int h0 = h0b + q * 4;
                float p0 = pjes[(size_t)(h0 + 0) * NN + j] + fmaf(filt, S->wes0[h0 + 0], S->pies[h0 + 0]);
                float p1 = pjes[(size_t)(h0 + 1) * NN + j] + fmaf(filt, S->wes0[h0 + 1], S->pies[h0 + 1]);
                float p2 = pjes[(size_t)(h0 + 2) * NN + j] + fmaf(filt, S->wes0[h0 + 2], S->pies[h0 + 2]);
                float p3 = pjes[(size_t)(h0 + 3) * NN + j] + fmaf(filt, S->wes0[h0 + 3], S->pies[h0 + 3]);
                float p4 = pjes[(size_t)(h0 + 4) * NN + j] + fmaf(filt, S->wes0[h0 + 4], S->pies[h0 + 4]);
                float p5 = pjes[(size_t)(h0 + 5) * NN + j] + fmaf(filt, S->wes0[h0 + 5], S->pies[h0 + 5]);
                float p6 = pjes[(size_t)(h0 + 6) * NN + j] + fmaf(filt, S->wes0[h0 + 6], S->pies[h0 + 6]);
                float p7 = pjes[(size_t)(h0 + 7) * NN + j] + fmaf(filt, S->wes0[h0 + 7], S->pies[h0 + 7]);
                u32 v0 = packh2(silu_hw(p0), silu_hw(p1));
                u32 v1 = packh2(silu_hw(p2), silu_hw(p3));
                u32 v2 = packh2(silu_hw(p4), silu_hw(p5));
                u32 v3 = packh2(silu_hw(p6), silu_hw(p7));
                STS128S(Aw_ad + (u32)(row * APAD16 + shalf * 16 + q * 2) * 4, v0, v1, v2, v3);
            }
        }
        __syncwarp();

        // ---- h_e_agg first: independent LDS+FMA overlaps the MMA fragment loads below ----
#pragma unroll 4
        for (int jj = 0; jj < 16; jj++) {
            float w = S->sw[jb + jj];
            u32 v = Aw16[jj * APAD16 + lane];
            __half2 h2v = *reinterpret_cast<__half2*>(&v);
            float2 f2 = __half22float2(h2v);
            agg0 = fmaf(w, f2.x, agg0);
            agg1 = fmaf(w, f2.y, agg1);
        }

        // ---- MMA: D[16j x 64m] = he @ W_c1 + b_c1, fp16 K=16 per step ----
        float D[8][4];
#pragma unroll
        for (int nt = 0; nt < 8; nt++) {
            const float bA = S->bc1[nt * 8 + 2 * c4], bB = S->bc1[nt * 8 + 2 * c4 + 1];
            D[nt][0] = bA; D[nt][1] = bB; D[nt][2] = bA; D[nt][3] = bB;
        }
#pragma unroll
        for (int kt = 0; kt < 4; kt++) {
            u32 a[4];
            a[0] = Aw16[r4 * APAD16 + kt * 8 + c4];
            a[1] = Aw16[(r4 + 8) * APAD16 + kt * 8 + c4];
            a[2] = Aw16[r4 * APAD16 + kt * 8 + 4 + c4];
            a[3] = Aw16[(r4 + 8) * APAD16 + kt * 8 + 4 + c4];
            const u32* bprow = S->Bpp + (kt << 9) + (c4 << 1);
#pragma unroll
            for (int nt = 0; nt < 8; nt++) {
                ull bv = *(const ull*)(bprow + ((nt * 8 + r4) << 3));
                mma_f16_16x8x16(D[nt], a, (u32)bv, (u32)(bv >> 32));
            }
        }

        // ---- epilogue: silu -> dot wc2 -> shuffle-free partial-coord x accumulation ----
        {
            float cs0 = bc2l, cs1 = bc2l;
#pragma unroll
            for (int nt = 0; nt < 8; nt++) {
                const int c0 = nt * 8 + 2 * c4, c1 = c0 + 1;
                const float wcA = S->wc2[c0], wcB = S->wc2[c1];
                cs0 = fmaf(silu_hw(D[nt][0]), wcA, cs0);
                cs0 = fmaf(silu_hw(D[nt][1]), wcB, cs0);
                cs1 = fmaf(silu_hw(D[nt][2]), wcA, cs1);
                cs1 = fmaf(silu_hw(D[nt][3]), wcB, cs1);
            }
            const int j0 = jb + r4, j1 = j0 + 8;
            float4 xv0 = S->xmxv[j0];
            float4 xv1 = S->xmxv[j1];
            xacc0 = fmaf(xv0.x, cs0, xacc0);
            xacc1 = fmaf(xv0.y, cs0, xacc1);
            xacc2 = fmaf(xv0.z, cs0, xacc2);
            xacc0 = fmaf(xv1.x, cs1, xacc0);
            xacc1 = fmaf(xv1.y, cs1, xacc1);
            xacc2 = fmaf(xv1.z, cs1, xacc2);
        }
        __syncwarp();   // A reused next subtile
    }

    // lane owns h = 2*lane (agg0), 2*lane+1 (agg1)
    S->aggp[warp][2 * lane]     = agg0;
    S->aggp[warp][2 * lane + 1] = agg1;
#pragma unroll
    for (int o = 16; o; o >>= 1) {
        xacc0 += __shfl_xor_sync(0xffffffffu, xacc0, o);
        xacc1 += __shfl_xor_sync(0xffffffffu, xacc1, o);
        xacc2 += __shfl_xor_sync(0xffffffffu, xacc2, o);
    }
    if (lane == 0) { S->xp[warp][0] = xacc0; S->xp[warp][1] = xacc1; S->xp[warp][2] = xacc2; }
    __syncthreads();

    // ---- finalize att_norm and h_e_agg (softmax scale folded in here) ----
    if (t < FD) {
        float a0 = S->attp[0][t][0] + S->attp[1][t][0] + S->attp[2][t][0] + S->attp[3][t][0];
        float a1 = S->attp[0][t][1] + S->attp[1][t][1] + S->attp[2][t][1] + S->attp[3][t][1];
        float a2 = S->attp[0][t][2] + S->attp[1][t][2] + S->attp[2][t][2] + S->attp[3][t][2];
        S->attn[t] = sqrtf(a0 * a0 + a1 * a1 + a2 * a2 + EPSV);
        float ag = 0.f;
#pragma unroll
        for (int w2 = 0; w2 < 8; w2++) ag += S->aggp[w2][t];
        S->agg[t] = ag * S->scal;
    }
    __syncthreads();

    // ---- h_new = concat(h, agg, attn) @ W_n + b_n ----
    if (t < FD) {
        int m = t;
        float acc = b_n[m];
        const float* hi2 = h + (size_t)n_i * FD;
#pragma unroll 8
        for (int f = 0; f < FD; f++)  acc = fmaf(hi2[f],      W_n[f * FD + m], acc);
#pragma unroll 8
        for (int f = 0; f < FD; f++)  acc = fmaf(S->agg[f],   W_n[(FD + f) * FD + m], acc);
#pragma unroll 8
        for (int f = 0; f < FD; f++)  acc = fmaf(S->attn[f],  W_n[(2 * FD + f) * FD + m], acc);
        out[(size_t)n_i * FD + m] = acc;
    }
    if (t >= 64 && t < 67) {
        int c = t - 64;
        float xs = 0.f;
#pragma unroll
        for (int w2 = 0; w2 < 8; w2++) xs += S->xp[w2][c];
        out[(size_t)BN * FD + n_i * 3 + c] = x[n_i * 3 + c] + xs;
    }
}

extern "C" void kernel_launch(void* const* d_in, const int* in_sizes, int n_in,
                              void* d_out, int out_size) {
    const float* h    = (const float*)d_in[0];
    const float* x    = (const float*)d_in[1];
    const float* W_ew = (const float*)d_in[2];
    const float* b_ew = (const float*)d_in[3];
    const float* W_sa = (const float*)d_in[4];
    const float* W_es = (const float*)d_in[5];
    const float* b_es = (const float*)d_in[6];
    const float* W_c1 = (const float*)d_in[7];
    const float* b_c1 = (const float*)d_in[8];
    const float* W_c2 = (const float*)d_in[9];
    const float* b_c2 = (const float*)d_in[10];
    const float* W_n  = (const float*)d_in[11];
    const float* b_n  = (const float*)d_in[12];
    float* out = (float*)d_out;

    const int smem_bytes = (int)sizeof(SMEM);
    cudaFuncSetAttribute(sake_main, cudaFuncAttributeMaxDynamicSharedMemorySize, smem_bytes);

    sake_pre<<<BN, 64>>>(h, W_ew, W_es, W_sa);
    sake_main<<<BN, 256, smem_bytes>>>(h, x, b_ew, W_es, b_es, W_c1, b_c1, W_c2, b_c2, W_n, b_n, out);
}